// round 5
// baseline (speedup 1.0000x reference)
#include <cuda_runtime.h>
#include <cstdint>

#define N_NODES 59392
#define F_IN    116
#define H_DIM   256
#define N_EDGES 950272
#define E_DIM   5
#define EMB     16
#define K_IN    (F_IN + EMB)   // 132
#define BN_EPS  1e-5f

// ---------------- scratch (no allocations allowed) ----------------
__device__ float g_h  [(size_t)N_NODES * H_DIM];
__device__ float g_agg[(size_t)N_NODES * H_DIM];
__device__ float g_tmp[(size_t)N_NODES * H_DIM];
__device__ float g_sum[H_DIM];
__device__ float g_sumsq[H_DIM];
__device__ float g_scale[H_DIM];
__device__ float g_shift[H_DIM];
__device__ int   g_src[N_EDGES];
__device__ int   g_dst[N_EDGES];
__device__ int   g_gid[N_NODES];
__device__ int   g_is64;

// ---------------- dtype probe: int64 vs int32 index buffers ----------------
__global__ void detect_kernel(const int* __restrict__ ei_words) {
    if (threadIdx.x == 0) {
        int all_zero = 1;
        for (int i = 1; i < 256; i += 2)
            if (ei_words[i] != 0) { all_zero = 0; break; }
        g_is64 = all_zero;
    }
}

// normalize edge_index and group_ids into int32 scratch (works for both dtypes)
__global__ __launch_bounds__(256)
void convert_kernel(const void* __restrict__ ei, const void* __restrict__ gid) {
    const int is64 = g_is64;
    const long long* ei64  = (const long long*)ei;
    const int*       ei32  = (const int*)ei;
    const long long* gid64 = (const long long*)gid;
    const int*       gid32 = (const int*)gid;
    size_t stride = (size_t)gridDim.x * blockDim.x;
    for (size_t e = (size_t)blockIdx.x * blockDim.x + threadIdx.x; e < N_EDGES; e += stride) {
        if (is64) {
            g_src[e] = (int)ei64[e];
            g_dst[e] = (int)ei64[(size_t)N_EDGES + e];
        } else {
            g_src[e] = ei32[e];
            g_dst[e] = ei32[(size_t)N_EDGES + e];
        }
    }
    for (size_t n = (size_t)blockIdx.x * blockDim.x + threadIdx.x; n < N_NODES; n += stride)
        g_gid[n] = is64 ? (int)gid64[n] : gid32[n];
}

// ---------------- zero agg + stats ----------------
__global__ __launch_bounds__(256)
void zero_kernel() {
    size_t total4 = (size_t)N_NODES * H_DIM / 4;
    size_t stride = (size_t)gridDim.x * blockDim.x;
    float4* a4 = reinterpret_cast<float4*>(g_agg);
    float4 z = make_float4(0.f, 0.f, 0.f, 0.f);
    for (size_t i = (size_t)blockIdx.x * blockDim.x + threadIdx.x; i < total4; i += stride)
        a4[i] = z;
    if (blockIdx.x == 0 && threadIdx.x < H_DIM) {
        g_sum[threadIdx.x]   = 0.0f;
        g_sumsq[threadIdx.x] = 0.0f;
    }
}

// ---------------- helpers ----------------
__device__ __forceinline__ unsigned f2tf32(float v) {
    unsigned r;
    asm("cvt.rna.tf32.f32 %0, %1;" : "=r"(r) : "f"(v));
    return r;
}
__device__ __forceinline__ void split_tf32(float v, unsigned& hi, unsigned& lo) {
    hi = f2tf32(v);
    lo = f2tf32(v - __uint_as_float(hi));
}
__device__ __forceinline__ void mma_tf32(float* c, const unsigned* a, const unsigned* b) {
    asm volatile(
        "mma.sync.aligned.m16n8k8.row.col.f32.tf32.tf32.f32 "
        "{%0,%1,%2,%3}, {%4,%5,%6,%7}, {%8,%9}, {%0,%1,%2,%3};\n"
        : "+f"(c[0]), "+f"(c[1]), "+f"(c[2]), "+f"(c[3])
        : "r"(a[0]), "r"(a[1]), "r"(a[2]), "r"(a[3]), "r"(b[0]), "r"(b[1]));
}

// ---------------- 3xTF32 tensor-core GEMM ----------------
// dst[M x 256] = relu(A[M x K] @ W[K x 256] + bias)
// MODE 0: A = concat(x, group_emb[g_gid])  (K = 132), dst = g_h
// MODE 1: A = g_h + g_agg                  (K = 256), dst = g_tmp
// MODE 2: A = g_tmp                        (K = 256), dst = out param
// BM=128, BN=128, BK=16, 256 threads = 8 warps (4x2), warp tile 32x64.
#define AS_STR 17    // As row stride (words)
#define BS_STR 132   // Bs row stride (words), 16B-aligned, conflict-free frags

template <int MODE>
__global__ __launch_bounds__(256, 2)
void gemm_kernel(const float* __restrict__ X,
                 const float* __restrict__ Gemb,
                 const float* __restrict__ W,
                 const float* __restrict__ bias,
                 float* __restrict__ out_param,
                 int K)
{
    const int BM = 128, BK = 16;
    __shared__ unsigned As_hi[BM * AS_STR];   // [m][k]
    __shared__ unsigned As_lo[BM * AS_STR];
    __shared__ __align__(16) unsigned Bs_hi[BK * BS_STR];  // [k][n]
    __shared__ __align__(16) unsigned Bs_lo[BK * BS_STR];
    __shared__ int sgid[BM];

    const int row0 = blockIdx.x * BM;
    const int col0 = blockIdx.y * 128;
    const int tid  = threadIdx.x;
    const int wid  = tid >> 5;
    const int lane = tid & 31;
    const int wm   = (wid & 3) * 32;   // warp row offset
    const int wn   = (wid >> 2) * 64;  // warp col offset
    const int lrow = lane >> 2;        // 0..7
    const int lkb  = lane & 3;         // 0..3

    if (MODE == 0) {
        if (tid < BM) sgid[tid] = g_gid[row0 + tid];
        __syncthreads();
    }

    float acc[2][8][4];
#pragma unroll
    for (int mt = 0; mt < 2; mt++)
#pragma unroll
        for (int nt = 0; nt < 8; nt++)
#pragma unroll
            for (int i = 0; i < 4; i++) acc[mt][nt][i] = 0.0f;

    const int ntiles = (K + BK - 1) / BK;
    for (int kt = 0; kt < ntiles; kt++) {
        const int k0 = kt * BK;

        // ---- stage A tile: 2 float4 per thread, split to hi/lo ----
#pragma unroll
        for (int i = 0; i < 2; i++) {
            int idx = tid + i * 256;          // 0..511
            int m   = idx >> 2;               // 0..127
            int kq  = (idx & 3) * 4;
            int row = row0 + m;
            float vv[4];
            if (MODE == 0) {
#pragma unroll
                for (int j = 0; j < 4; j++) {
                    int kj = k0 + kq + j;
                    vv[j] = (kj < K) ? ((kj < F_IN) ? X[(size_t)row * F_IN + kj]
                                                    : Gemb[sgid[m] * EMB + (kj - F_IN)])
                                     : 0.0f;
                }
            } else if (MODE == 1) {
                float4 a = *reinterpret_cast<const float4*>(&g_h  [(size_t)row * H_DIM + k0 + kq]);
                float4 b = *reinterpret_cast<const float4*>(&g_agg[(size_t)row * H_DIM + k0 + kq]);
                vv[0] = a.x + b.x; vv[1] = a.y + b.y; vv[2] = a.z + b.z; vv[3] = a.w + b.w;
            } else {
                float4 a = *reinterpret_cast<const float4*>(&g_tmp[(size_t)row * H_DIM + k0 + kq]);
                vv[0] = a.x; vv[1] = a.y; vv[2] = a.z; vv[3] = a.w;
            }
#pragma unroll
            for (int j = 0; j < 4; j++) {
                unsigned hi, lo;
                split_tf32(vv[j], hi, lo);
                As_hi[m * AS_STR + kq + j] = hi;
                As_lo[m * AS_STR + kq + j] = lo;
            }
        }
        // ---- stage B tile: 2 float4 per thread, split to hi/lo ----
#pragma unroll
        for (int i = 0; i < 2; i++) {
            int idx = tid + i * 256;          // 0..511
            int kk  = idx >> 5;               // 0..15
            int n   = (idx & 31) * 4;         // 0..124
            int k   = k0 + kk;
            float4 v = make_float4(0.f, 0.f, 0.f, 0.f);
            if (k < K)
                v = *reinterpret_cast<const float4*>(&W[(size_t)k * H_DIM + col0 + n]);
            unsigned h0,h1,h2,h3,l0,l1,l2,l3;
            split_tf32(v.x, h0, l0); split_tf32(v.y, h1, l1);
            split_tf32(v.z, h2, l2); split_tf32(v.w, h3, l3);
            *reinterpret_cast<uint4*>(&Bs_hi[kk * BS_STR + n]) = make_uint4(h0,h1,h2,h3);
            *reinterpret_cast<uint4*>(&Bs_lo[kk * BS_STR + n]) = make_uint4(l0,l1,l2,l3);
        }
        __syncthreads();

        // ---- mainloop: 2 k8-steps ----
#pragma unroll
        for (int ks = 0; ks < 2; ks++) {
            const int kb = ks * 8;
            unsigned ah[2][4], al[2][4];
#pragma unroll
            for (int mt = 0; mt < 2; mt++) {
                int mrow = wm + mt * 16 + lrow;
                int kc   = kb + lkb;
                ah[mt][0] = As_hi[ mrow      * AS_STR + kc];
                ah[mt][1] = As_hi[(mrow + 8) * AS_STR + kc];
                ah[mt][2] = As_hi[ mrow      * AS_STR + kc + 4];
                ah[mt][3] = As_hi[(mrow + 8) * AS_STR + kc + 4];
                al[mt][0] = As_lo[ mrow      * AS_STR + kc];
                al[mt][1] = As_lo[(mrow + 8) * AS_STR + kc];
                al[mt][2] = As_lo[ mrow      * AS_STR + kc + 4];
                al[mt][3] = As_lo[(mrow + 8) * AS_STR + kc + 4];
            }
#pragma unroll
            for (int nt = 0; nt < 8; nt++) {
                int ncol = wn + nt * 8 + lrow;
                unsigned bh[2], bl[2];
                bh[0] = Bs_hi[(kb + lkb)     * BS_STR + ncol];
                bh[1] = Bs_hi[(kb + lkb + 4) * BS_STR + ncol];
                bl[0] = Bs_lo[(kb + lkb)     * BS_STR + ncol];
                bl[1] = Bs_lo[(kb + lkb + 4) * BS_STR + ncol];
#pragma unroll
                for (int mt = 0; mt < 2; mt++) {
                    mma_tf32(acc[mt][nt], ah[mt], bh);   // Ah*Bh
                    mma_tf32(acc[mt][nt], ah[mt], bl);   // Ah*Bl
                    mma_tf32(acc[mt][nt], al[mt], bh);   // Al*Bh
                }
            }
        }
        __syncthreads();
    }

    // ---- epilogue: bias + relu, float2 stores ----
    float* dst = (MODE == 0) ? g_h : (MODE == 1) ? g_tmp : out_param;
    const int cb = (lane & 3) * 2;     // col pair base within n8 tile
#pragma unroll
    for (int nt = 0; nt < 8; nt++) {
        int col = col0 + wn + nt * 8 + cb;
        float bx = bias[col], by = bias[col + 1];
#pragma unroll
        for (int mt = 0; mt < 2; mt++) {
            int r = row0 + wm + mt * 16 + lrow;
            float2 w0 = make_float2(fmaxf(acc[mt][nt][0] + bx, 0.f),
                                    fmaxf(acc[mt][nt][1] + by, 0.f));
            float2 w1 = make_float2(fmaxf(acc[mt][nt][2] + bx, 0.f),
                                    fmaxf(acc[mt][nt][3] + by, 0.f));
            *reinterpret_cast<float2*>(&dst[(size_t)r * H_DIM + col])       = w0;
            *reinterpret_cast<float2*>(&dst[(size_t)(r + 8) * H_DIM + col]) = w1;
        }
    }
}

// ---------------- BatchNorm ----------------
__global__ __launch_bounds__(256)
void bn_stats_kernel() {
    int c = threadIdx.x;   // 256 channels
    float s = 0.0f, s2 = 0.0f;
    for (int r = blockIdx.x; r < N_NODES; r += gridDim.x) {
        float v = g_h[(size_t)r * H_DIM + c];
        s += v;
        s2 += v * v;
    }
    atomicAdd(&g_sum[c], s);
    atomicAdd(&g_sumsq[c], s2);
}

__global__ void bn_finalize_kernel(const float* __restrict__ gamma,
                                   const float* __restrict__ beta) {
    int c = threadIdx.x;
    float invN = 1.0f / (float)N_NODES;
    float mu   = g_sum[c] * invN;
    float var  = fmaxf(g_sumsq[c] * invN - mu * mu, 0.0f);
    float rs   = rsqrtf(var + BN_EPS);
    float sc   = rs * gamma[c];
    g_scale[c] = sc;
    g_shift[c] = beta[c] - mu * sc;
}

__global__ __launch_bounds__(256)
void bn_apply_kernel() {
    size_t total4 = (size_t)N_NODES * H_DIM / 4;
    size_t stride = (size_t)gridDim.x * blockDim.x;
    float4* h4 = reinterpret_cast<float4*>(g_h);
    for (size_t i = (size_t)blockIdx.x * blockDim.x + threadIdx.x; i < total4; i += stride) {
        int c0 = (int)((i * 4) & (H_DIM - 1));
        float4 v = h4[i];
        v.x = v.x * g_scale[c0 + 0] + g_shift[c0 + 0];
        v.y = v.y * g_scale[c0 + 1] + g_shift[c0 + 1];
        v.z = v.z * g_scale[c0 + 2] + g_shift[c0 + 2];
        v.w = v.w * g_scale[c0 + 3] + g_shift[c0 + 3];
        h4[i] = v;
    }
}

// ---------------- GINE edge kernel ----------------
// warp per edge (grid-stride). lane owns cols [8*lane, 8*lane+8).
__global__ __launch_bounds__(256)
void edge_kernel(const float* __restrict__ ea,
                 const float* __restrict__ We,
                 const float* __restrict__ be)
{
    const int lane   = threadIdx.x & 31;
    const int warp   = (blockIdx.x * blockDim.x + threadIdx.x) >> 5;
    const int nwarps = (gridDim.x * blockDim.x) >> 5;
    const int cbase  = lane * 8;

    float we[E_DIM][8], bvec[8];
#pragma unroll
    for (int d = 0; d < E_DIM; d++)
#pragma unroll
        for (int j = 0; j < 8; j++)
            we[d][j] = We[d * H_DIM + cbase + j];
#pragma unroll
    for (int j = 0; j < 8; j++) bvec[j] = be[cbase + j];

    for (int e = warp; e < N_EDGES; e += nwarps) {
        int src = g_src[e];
        int dst = g_dst[e];
        float eav = (lane < E_DIM) ? ea[(size_t)e * E_DIM + lane] : 0.0f;

        float acc[8];
#pragma unroll
        for (int j = 0; j < 8; j++) acc[j] = bvec[j];
#pragma unroll
        for (int d = 0; d < E_DIM; d++) {
            float v = __shfl_sync(0xffffffffu, eav, d);
#pragma unroll
            for (int j = 0; j < 8; j++) acc[j] = fmaf(v, we[d][j], acc[j]);
        }

        const float4* hp = reinterpret_cast<const float4*>(&g_h[(size_t)src * H_DIM + cbase]);
        float4 h0 = hp[0];
        float4 h1 = hp[1];

        float m0 = fmaxf(h0.x + acc[0], 0.0f);
        float m1 = fmaxf(h0.y + acc[1], 0.0f);
        float m2 = fmaxf(h0.z + acc[2], 0.0f);
        float m3 = fmaxf(h0.w + acc[3], 0.0f);
        float m4 = fmaxf(h1.x + acc[4], 0.0f);
        float m5 = fmaxf(h1.y + acc[5], 0.0f);
        float m6 = fmaxf(h1.z + acc[6], 0.0f);
        float m7 = fmaxf(h1.w + acc[7], 0.0f);

        float* ap = &g_agg[(size_t)dst * H_DIM + cbase];
        unsigned long long gaddr = (unsigned long long)__cvta_generic_to_global((void*)ap);
        asm volatile("red.global.add.v4.f32 [%0], {%1,%2,%3,%4};"
                     :: "l"(gaddr), "f"(m0), "f"(m1), "f"(m2), "f"(m3) : "memory");
        asm volatile("red.global.add.v4.f32 [%0], {%1,%2,%3,%4};"
                     :: "l"(gaddr + 16), "f"(m4), "f"(m5), "f"(m6), "f"(m7) : "memory");
    }
}

// ---------------- edge_attr passthrough (2nd tuple element) ----------------
__global__ __launch_bounds__(256)
void copy_kernel(const float* __restrict__ src, float* __restrict__ dst, size_t n4) {
    size_t stride = (size_t)gridDim.x * blockDim.x;
    const float4* s4 = reinterpret_cast<const float4*>(src);
    float4* d4 = reinterpret_cast<float4*>(dst);
    for (size_t i = (size_t)blockIdx.x * blockDim.x + threadIdx.x; i < n4; i += stride)
        d4[i] = s4[i];
}

// ---------------- launch ----------------
extern "C" void kernel_launch(void* const* d_in, const int* in_sizes, int n_in,
                              void* d_out, int out_size)
{
    // ---- input order detection by size signature ----
    static const long long SZ_DICT[15] = {
        6889472LL, 1900544LL, 4751360LL, 59392LL, 128LL, 33792LL, 256LL,
        256LL, 256LL, 1280LL, 256LL, 65536LL, 256LL, 65536LL, 256LL };
    static const long long SZ_ALPHA[15] = {
        65536LL, 65536LL, 33792LL, 1280LL, 256LL, 256LL, 256LL, 256LL,
        256LL, 4751360LL, 1900544LL, 256LL, 128LL, 59392LL, 6889472LL };
    static const int ALPHA_TO_DICT[15] = { 11, 13, 5, 9, 12, 14, 6, 10, 8, 2, 1, 7, 4, 3, 0 };

    int perm[15];
    for (int i = 0; i < 15; i++) perm[i] = i;
    if (n_in >= 15) {
        bool dict_ok = true, alpha_ok = true;
        for (int i = 0; i < 15; i++) {
            if ((long long)in_sizes[i] != SZ_DICT[i])  dict_ok  = false;
            if ((long long)in_sizes[i] != SZ_ALPHA[i]) alpha_ok = false;
        }
        if (!dict_ok && alpha_ok)
            for (int i = 0; i < 15; i++) perm[ALPHA_TO_DICT[i]] = i;
    }

    const float* x      = (const float*)d_in[perm[0]];
    const void*  eindex = d_in[perm[1]];
    const float* eattr  = (const float*)d_in[perm[2]];
    const void*  gids   = d_in[perm[3]];
    const float* gemb   = (const float*)d_in[perm[4]];
    const float* W_in   = (const float*)d_in[perm[5]];
    const float* b_in   = (const float*)d_in[perm[6]];
    const float* gamma  = (const float*)d_in[perm[7]];
    const float* beta   = (const float*)d_in[perm[8]];
    const float* We     = (const float*)d_in[perm[9]];
    const float* be     = (const float*)d_in[perm[10]];
    const float* W1     = (const float*)d_in[perm[11]];
    const float* b1     = (const float*)d_in[perm[12]];
    const float* W2     = (const float*)d_in[perm[13]];
    const float* b2     = (const float*)d_in[perm[14]];
    float* out = (float*)d_out;

    dim3 ggrid(N_NODES / 128, H_DIM / 128);   // (464, 2)

    // 0. dtype probe + index normalization (int64 vs int32)
    detect_kernel<<<1, 32>>>((const int*)eindex);
    convert_kernel<<<2048, 256>>>(eindex, gids);

    // 1. zero agg + stats
    zero_kernel<<<2048, 256>>>();

    // 2. h = relu(concat(x, emb) @ W_in + b_in)   -> g_h
    gemm_kernel<0><<<ggrid, 256>>>(x, gemb, W_in, b_in, nullptr, K_IN);

    // 3-5. BatchNorm (training stats, biased var), applied in-place on g_h
    bn_stats_kernel<<<464, 256>>>();
    bn_finalize_kernel<<<1, 256>>>(gamma, beta);
    bn_apply_kernel<<<1024, 256>>>();

    // 6. GINE edge scatter: agg[dst] += relu(h[src] + ea@We + be)
    edge_kernel<<<4096, 256>>>(eattr, We, be);

    // 7. tmp = relu((h + agg) @ W1 + b1)   -> g_tmp
    gemm_kernel<1><<<ggrid, 256>>>(nullptr, nullptr, W1, b1, nullptr, H_DIM);

    // 8. out = relu(tmp @ W2 + b2)         -> d_out
    gemm_kernel<2><<<ggrid, 256>>>(nullptr, nullptr, W2, b2, out, H_DIM);

    // 9. second tuple element: edge_attr passthrough (size derived from out_size)
    long long tail = (long long)out_size - (long long)N_NODES * H_DIM;
    if (tail > 0) {
        size_t n4 = (size_t)tail / 4;
        copy_kernel<<<2048, 256>>>(eattr, out + (size_t)N_NODES * H_DIM, n4);
    }
}